// round 3
// baseline (speedup 1.0000x reference)
#include <cuda_runtime.h>
#include <cuda_bf16.h>

#define PADDING_IDX 0
#define SMOOTHING   0.1f

// Scratch for per-row partial contributions (N = 4096; padded for safety).
// __device__ globals: allocation-free per harness rules.
#define MAX_ROWS 8192
__device__ float        g_row_partial[MAX_ROWS];
__device__ unsigned int g_done_count = 0;   // reset to 0 by the last block each launch

// One block per row. Computes
//   partial[r] = mask_r * ( -(SMOOTHING/V) * sum_v x[r,v]  -  (1-SMOOTHING) * x[r, target_r] )
// then the LAST block to finish reduces all partials to the scalar output
// (threadfence-reduction pattern) — saves a second kernel launch (~5.5us).
// NOTE: target is int32 on device (JAX x64-disabled downcasts int64 -> int32).
__global__ void __launch_bounds__(256)
ls_fused_kernel(const float* __restrict__ x,
                const int* __restrict__ target,
                float* __restrict__ out,
                int V, int N)
{
    const int r = blockIdx.x;
    const int t = target[r];
    const bool valid = (t != PADDING_IDX) && (t >= 0) && (t < V);

    __shared__ float sh[8];        // 8 warps
    __shared__ bool  sh_is_last;

    if (valid) {
        const size_t row_off = (size_t)r * (size_t)V;
        const float4* __restrict__ row4 = reinterpret_cast<const float4*>(x + row_off);
        const int nv4 = V >> 2;    // V = 32000 -> 8000 float4 chunks (16B-aligned rows)

        float s = 0.0f;
        // Coalesced 128B wavefronts; ~31 iters/thread -> deep MLP, DRAM latency hidden.
        for (int i = threadIdx.x; i < nv4; i += blockDim.x) {
            float4 v = row4[i];
            s += (v.x + v.y) + (v.z + v.w);
        }
        for (int i = (nv4 << 2) + threadIdx.x; i < V; i += blockDim.x)
            s += x[row_off + i];   // tail (not hit for V=32000)

        #pragma unroll
        for (int o = 16; o > 0; o >>= 1)
            s += __shfl_down_sync(0xffffffffu, s, o);
        if ((threadIdx.x & 31) == 0) sh[threadIdx.x >> 5] = s;
        __syncthreads();

        if (threadIdx.x < 32) {
            float v = (threadIdx.x < 8) ? sh[threadIdx.x] : 0.0f;
            #pragma unroll
            for (int o = 4; o > 0; o >>= 1)
                v += __shfl_down_sync(0xffffffffu, v, o);
            if (threadIdx.x == 0) {
                const float g = x[row_off + (size_t)t];   // gather, L2-hot
                g_row_partial[r] = -(SMOOTHING / (float)V) * v - (1.0f - SMOOTHING) * g;
            }
        }
    } else {
        if (threadIdx.x == 0) g_row_partial[r] = 0.0f;
    }

    // ---- last-block final reduction ----
    if (threadIdx.x == 0) {
        __threadfence();                                   // publish g_row_partial[r]
        unsigned int done = atomicAdd(&g_done_count, 1u);
        sh_is_last = (done == (unsigned int)(gridDim.x - 1));
    }
    __syncthreads();

    if (sh_is_last) {
        __threadfence();                                   // see all partials
        float s = 0.0f;
        for (int i = threadIdx.x; i < N; i += blockDim.x)
            s += g_row_partial[i];

        #pragma unroll
        for (int o = 16; o > 0; o >>= 1)
            s += __shfl_down_sync(0xffffffffu, s, o);
        if ((threadIdx.x & 31) == 0) sh[threadIdx.x >> 5] = s;
        __syncthreads();

        if (threadIdx.x < 32) {
            float v = (threadIdx.x < 8) ? sh[threadIdx.x] : 0.0f;
            #pragma unroll
            for (int o = 4; o > 0; o >>= 1)
                v += __shfl_down_sync(0xffffffffu, v, o);
            if (threadIdx.x == 0) {
                out[0] = v;
                g_done_count = 0;   // reset for next graph replay (deterministic)
            }
        }
    }
}

extern "C" void kernel_launch(void* const* d_in, const int* in_sizes, int n_in,
                              void* d_out, int out_size)
{
    const float* x      = (const float*)d_in[0];
    const int*   target = (const int*)d_in[1];
    float*       out    = (float*)d_out;

    const int N = in_sizes[1];         // 4096 rows
    const int V = in_sizes[0] / N;     // 32000 vocab

    ls_fused_kernel<<<N, 256>>>(x, target, out, V, N);
}

// round 4
// speedup vs baseline: 1.1004x; 1.1004x over previous
#include <cuda_runtime.h>
#include <cuda_bf16.h>

#define PADDING_IDX 0
#define SMOOTHING   0.1f

// Scratch for per-row partial contributions (N = 4096; padded for safety).
// __device__ global: allocation-free per harness rules.
#define MAX_ROWS 8192
__device__ float g_row_partial[MAX_ROWS];

// One block per row. Computes
//   partial[r] = mask_r * ( -(SMOOTHING/V) * sum_v x[r,v]  -  (1-SMOOTHING) * x[r, target_r] )
// NOTE: target is int32 on device (JAX x64-disabled downcasts int64 -> int32).
__global__ void __launch_bounds__(256)
ls_row_kernel(const float* __restrict__ x,
              const int* __restrict__ target,
              int V)
{
    const int r = blockIdx.x;
    const int t = target[r];

    // Padding row, or (defensively) any out-of-range index: contributes 0,
    // and we skip streaming the row entirely.
    if (t == PADDING_IDX || t < 0 || t >= V) {
        if (threadIdx.x == 0) g_row_partial[r] = 0.0f;
        return;
    }

    const size_t row_off = (size_t)r * (size_t)V;
    const float4* __restrict__ row4 = reinterpret_cast<const float4*>(x + row_off);
    const int nv4 = V >> 2;    // V = 32000 -> 8000 float4 chunks (16B-aligned rows)

    float s = 0.0f;
    // Consecutive threads hit consecutive 16B chunks -> fully coalesced
    // 128B wavefronts; ~31 iters/thread -> deep MLP, DRAM latency hidden.
    for (int i = threadIdx.x; i < nv4; i += blockDim.x) {
        float4 v = row4[i];
        s += (v.x + v.y) + (v.z + v.w);
    }
    for (int i = (nv4 << 2) + threadIdx.x; i < V; i += blockDim.x)
        s += x[row_off + i];   // tail (not hit for V=32000)

    // Warp reduce
    #pragma unroll
    for (int o = 16; o > 0; o >>= 1)
        s += __shfl_down_sync(0xffffffffu, s, o);

    __shared__ float sh[8];    // 8 warps
    if ((threadIdx.x & 31) == 0) sh[threadIdx.x >> 5] = s;
    __syncthreads();

    if (threadIdx.x < 32) {
        float v = (threadIdx.x < 8) ? sh[threadIdx.x] : 0.0f;
        #pragma unroll
        for (int o = 4; o > 0; o >>= 1)
            v += __shfl_down_sync(0xffffffffu, v, o);
        if (threadIdx.x == 0) {
            const float g = x[row_off + (size_t)t];   // gather, L2-hot
            g_row_partial[r] = -(SMOOTHING / (float)V) * v - (1.0f - SMOOTHING) * g;
        }
    }
}

// Deterministic single-block reduction of N row partials -> scalar.
// Shuffle-based: one __syncthreads() total (vs 10-level smem tree before).
// Partials are L2-hot (just written by ls_row_kernel).
__global__ void __launch_bounds__(256)
ls_final_kernel(float* __restrict__ out, int n)
{
    const float4* __restrict__ p4 = reinterpret_cast<const float4*>(g_row_partial);
    const int n4 = n >> 2;     // 4096 -> 1024 float4

    float s = 0.0f;
    for (int i = threadIdx.x; i < n4; i += 256) {      // 4 iters @ n=4096
        float4 v = p4[i];
        s += (v.x + v.y) + (v.z + v.w);
    }
    for (int i = (n4 << 2) + threadIdx.x; i < n; i += 256)
        s += g_row_partial[i];                         // tail (unused for 4096)

    #pragma unroll
    for (int o = 16; o > 0; o >>= 1)
        s += __shfl_down_sync(0xffffffffu, s, o);

    __shared__ float sh[8];
    if ((threadIdx.x & 31) == 0) sh[threadIdx.x >> 5] = s;
    __syncthreads();

    if (threadIdx.x < 32) {
        float v = (threadIdx.x < 8) ? sh[threadIdx.x] : 0.0f;
        #pragma unroll
        for (int o = 4; o > 0; o >>= 1)
            v += __shfl_down_sync(0xffffffffu, v, o);
        if (threadIdx.x == 0) out[0] = v;
    }
}

extern "C" void kernel_launch(void* const* d_in, const int* in_sizes, int n_in,
                              void* d_out, int out_size)
{
    const float* x      = (const float*)d_in[0];
    const int*   target = (const int*)d_in[1];
    float*       out    = (float*)d_out;

    const int N = in_sizes[1];         // 4096 rows
    const int V = in_sizes[0] / N;     // 32000 vocab

    ls_row_kernel<<<N, 256>>>(x, target, V);
    ls_final_kernel<<<1, 256>>>(out, N);
}